// round 4
// baseline (speedup 1.0000x reference)
#include <cuda_runtime.h>
#include <cstdint>

// Problem dims
#define TT 2048
#define BB 64
#define DD 128
#define HH 256
#define CC 5

// 134 MB scratch for x_proj (allowed: __device__ global, no runtime alloc)
__device__ float g_xproj[TT * BB * HH];

// ---------- helpers ----------
__device__ __forceinline__ float2 up2(unsigned long long v) {
    float2 r;
    asm("mov.b64 {%0,%1}, %2;" : "=f"(r.x), "=f"(r.y) : "l"(v));
    return r;
}
#define FMA2(d, a, b) asm("fma.rn.f32x2 %0, %1, %2, %0;" : "+l"(d) : "l"(a), "l"(b))

__device__ __forceinline__ uint32_t smem_u32(const void* p) {
    uint32_t a;
    asm("{ .reg .u64 t; cvta.to.shared.u64 t, %1; cvt.u32.u64 %0, t; }" : "=r"(a) : "l"(p));
    return a;
}

// =====================================================================
// Kernel 1: x_proj[t,b,j] = sum_k inputs[t,b,k] * W_ih[j,k] + b_ih[j] + b_hh[j]
// grid = 2048 (one t per CTA), 256 threads, f32x2 paired over k.
// =====================================================================
#define WPAD 130  // floats per W row in smem (520B: 8B-aligned, 2-way LDS conflict only)

__global__ __launch_bounds__(256) void xproj_kernel(
    const float* __restrict__ x, const float* __restrict__ Wih,
    const float* __restrict__ bih, const float* __restrict__ bhh)
{
    extern __shared__ float sm[];
    float* Wsm = sm;                    // [256][WPAD]
    float* Xsm = sm + 256 * WPAD;       // [64][128]
    const int t = blockIdx.x, tid = threadIdx.x;

    // stage W_ih (coalesced read, conflict-free write: consecutive k same row)
    for (int i = tid; i < 256 * 128; i += 256) {
        int j = i >> 7, k = i & 127;
        Wsm[j * WPAD + k] = Wih[i];
    }
    // stage x[t]
    const float* xt = x + (size_t)t * BB * DD;
    for (int i = tid; i < BB * DD; i += 256) Xsm[i] = xt[i];
    __syncthreads();

    const int bx = tid >> 5;   // 0..7  -> b in [8bx, 8bx+8)
    const int jx = tid & 31;   // 0..31 -> j in {jx + 32c}

    float bsum[8];
#pragma unroll
    for (int c = 0; c < 8; c++) {
        int j = jx + 32 * c;
        bsum[c] = bih[j] + bhh[j];
    }

    unsigned long long acc[8][8];
#pragma unroll
    for (int b = 0; b < 8; b++)
#pragma unroll
        for (int c = 0; c < 8; c++) acc[b][c] = 0ULL;

    const unsigned long long* Wu = (const unsigned long long*)Wsm;  // row stride 65 ull
    const unsigned long long* Xu = (const unsigned long long*)Xsm;  // row stride 64 ull

#pragma unroll 2
    for (int kp = 0; kp < 64; kp++) {
        unsigned long long w[8];
#pragma unroll
        for (int c = 0; c < 8; c++) w[c] = Wu[(jx + 32 * c) * 65 + kp];
#pragma unroll
        for (int b = 0; b < 8; b++) {
            unsigned long long a = Xu[(bx * 8 + b) * 64 + kp];
#pragma unroll
            for (int c = 0; c < 8; c++) FMA2(acc[b][c], w[c], a);
        }
    }

    float* op = g_xproj + (size_t)t * BB * HH;
#pragma unroll
    for (int b = 0; b < 8; b++) {
#pragma unroll
        for (int c = 0; c < 8; c++) {
            float2 f = up2(acc[b][c]);
            op[(bx * 8 + b) * HH + jx + 32 * c] = f.x + f.y + bsum[c];
        }
    }
}

// =====================================================================
// Kernel 2: persistent recurrence + head.
// 64 clusters of 2 CTAs (one batch per cluster). CTA rank r holds W_hh rows
// [128r, 128r+128) in REGISTERS (32 floats/thread). Per step: f32x2 matvec,
// smem partial reduce, tanh, DSMEM exchange of h halves, mbarrier sync.
// =====================================================================
__global__ void __launch_bounds__(1024, 1) __cluster_dims__(2, 1, 1)
rnn_kernel(const float* __restrict__ Whh, const float* __restrict__ Wfc,
           const float* __restrict__ bfc, float* __restrict__ out)
{
    __shared__ __align__(16) float hbuf[2][HH];
    __shared__ float psum[1024];
    __shared__ __align__(8) unsigned long long mbar_store;
    __shared__ float logits_sm[8];

    const int tid  = threadIdx.x;
    const int rank = blockIdx.x & 1;
    const int b    = blockIdx.x >> 1;
    const int jl   = tid & 127;   // output row within this CTA's half
    const int g    = tid >> 7;    // k-group (32 k each), warp-uniform

    // --- load this thread's W_hh slice into registers (16 f32x2 pairs) ---
    unsigned long long W2[16];
    {
        const ulonglong2* p =
            (const ulonglong2*)(Whh + (size_t)(rank * 128 + jl) * HH + g * 32);
#pragma unroll
        for (int m = 0; m < 8; m++) {
            ulonglong2 v = p[m];
            W2[2 * m]     = v.x;
            W2[2 * m + 1] = v.y;
        }
    }

    // init h0 = 0
    for (int i = tid; i < HH; i += 1024) hbuf[0][i] = 0.0f;

    const uint32_t mbar_local = smem_u32(&mbar_store);
    if (tid == 0) {
        asm volatile("mbarrier.init.shared.b64 [%0], %1;"
                     :: "r"(mbar_local), "r"(128) : "memory");
    }
    __syncthreads();
    // cluster barrier: peer mbarrier must be initialized before cross-arrives
    asm volatile("barrier.cluster.arrive.aligned;" ::: "memory");
    asm volatile("barrier.cluster.wait.aligned;" ::: "memory");

    const uint32_t peer = rank ^ 1;
    uint32_t mbar_peer, hbuf_peer;
    asm("mapa.shared::cluster.u32 %0, %1, %2;" : "=r"(mbar_peer)
        : "r"(mbar_local), "r"(peer));
    asm("mapa.shared::cluster.u32 %0, %1, %2;" : "=r"(hbuf_peer)
        : "r"(smem_u32(&hbuf[0][0])), "r"(peer));

    const float* xrow = g_xproj + (size_t)b * HH + rank * 128 + tid;  // valid for tid<128
    const int xstride = BB * HH;

    int ph = 0, p = 0;
    float xp_cur = 0.0f, xp_next = 0.0f;
    if (tid < 128) xp_cur = xrow[0];

    for (int t = 0; t < TT; t++) {
        if (tid < 128 && t + 1 < TT) xp_next = xrow[(size_t)(t + 1) * xstride];

        // --- matvec partial: this thread covers k in [32g, 32g+32) ---
        const ulonglong2* hu = (const ulonglong2*)(&hbuf[p][g * 32]);
        unsigned long long a0 = 0ULL, a1 = 0ULL;
#pragma unroll
        for (int m = 0; m < 8; m++) {
            ulonglong2 hh = hu[m];
            FMA2(a0, W2[2 * m],     hh.x);
            FMA2(a1, W2[2 * m + 1], hh.y);
        }
        float2 f0 = up2(a0), f1 = up2(a1);
        psum[tid] = (f0.x + f0.y) + (f1.x + f1.y);
        __syncthreads();

        // --- reduce 8 partials, tanh, publish to both CTAs ---
        if (tid < 128) {
            float r = psum[tid];
#pragma unroll
            for (int gg = 1; gg < 8; gg++) r += psum[tid + 128 * gg];
            float hn = tanhf(r + xp_cur);
            int pn = p ^ 1;
            hbuf[pn][rank * 128 + tid] = hn;  // own copy
            uint32_t dst = hbuf_peer + (uint32_t)((pn * HH + rank * 128 + tid) * 4);
            asm volatile("st.shared::cluster.f32 [%0], %1;"
                         :: "r"(dst), "f"(hn) : "memory");
            asm volatile("mbarrier.arrive.release.cluster.shared::cluster.b64 _, [%0];"
                         :: "r"(mbar_peer) : "memory");
        }
        __syncthreads();  // own half visible CTA-wide

        // --- wait for peer's 128 arrivals (acquire, cluster scope) ---
        asm volatile(
            "{\n\t.reg .pred P;\n"
            "W%=:\n\t"
            "mbarrier.try_wait.parity.acquire.cluster.shared::cta.b64 P, [%0], %1;\n\t"
            "@!P bra W%=;\n\t}"
            :: "r"(mbar_local), "r"(ph) : "memory");

        ph ^= 1;
        p ^= 1;
        xp_cur = xp_next;
    }

    // --- head: rank 0 computes logits + log_softmax for its batch ---
    // after loop, p == 0 and hbuf[0] holds h_last (full 256)
    if (rank == 0) {
        const int w = tid >> 5, l = tid & 31;
        if (w < CC) {
            float s = 0.0f;
#pragma unroll
            for (int q = 0; q < 8; q++)
                s += hbuf[p][l + 32 * q] * Wfc[w * HH + l + 32 * q];
#pragma unroll
            for (int off = 16; off > 0; off >>= 1)
                s += __shfl_xor_sync(0xffffffffu, s, off);
            if (l == 0) logits_sm[w] = s + bfc[w];
        }
        __syncthreads();
        if (tid == 0) {
            float m = logits_sm[0];
#pragma unroll
            for (int c = 1; c < CC; c++) m = fmaxf(m, logits_sm[c]);
            float se = 0.0f;
#pragma unroll
            for (int c = 0; c < CC; c++) se += expf(logits_sm[c] - m);
            float lse = logf(se);
#pragma unroll
            for (int c = 0; c < CC; c++)
                out[b * CC + c] = logits_sm[c] - m - lse;
        }
    }
}

// =====================================================================
// launch
// =====================================================================
extern "C" void kernel_launch(void* const* d_in, const int* in_sizes, int n_in,
                              void* d_out, int out_size)
{
    const float* inputs = (const float*)d_in[0];
    const float* W_ih   = (const float*)d_in[1];
    const float* W_hh   = (const float*)d_in[2];
    const float* b_ih   = (const float*)d_in[3];
    const float* b_hh   = (const float*)d_in[4];
    const float* W_fc   = (const float*)d_in[5];
    const float* b_fc   = (const float*)d_in[6];
    float* out = (float*)d_out;

    const int smem1 = (256 * WPAD + BB * DD) * (int)sizeof(float);  // ~166 KB
    static int configured = 0;
    if (!configured) {
        cudaFuncSetAttribute(xproj_kernel,
                             cudaFuncAttributeMaxDynamicSharedMemorySize, smem1);
        configured = 1;
    }

    xproj_kernel<<<TT, 256, smem1>>>(inputs, W_ih, b_ih, b_hh);
    rnn_kernel<<<2 * BB, 1024>>>(W_hh, W_fc, b_fc, out);
}

// round 5
// speedup vs baseline: 1.6556x; 1.6556x over previous
#include <cuda_runtime.h>
#include <cstdint>

// Problem dims
#define TT 2048
#define BB 64
#define DD 128
#define HH 256
#define CC 5

// 134 MB scratch for x_proj (allowed: __device__ global, no runtime alloc)
__device__ float g_xproj[TT * BB * HH];

// ---------- helpers ----------
__device__ __forceinline__ float2 up2(unsigned long long v) {
    float2 r;
    asm("mov.b64 {%0,%1}, %2;" : "=f"(r.x), "=f"(r.y) : "l"(v));
    return r;
}
#define FMA2(d, a, b) asm("fma.rn.f32x2 %0, %1, %2, %0;" : "+l"(d) : "l"(a), "l"(b))

__device__ __forceinline__ uint32_t smem_u32(const void* p) {
    uint32_t a;
    asm("{ .reg .u64 t; cvta.to.shared.u64 t, %1; cvt.u32.u64 %0, t; }" : "=r"(a) : "l"(p));
    return a;
}

// fast accurate-enough tanh: err ~5e-7, clamped to avoid exp overflow
__device__ __forceinline__ float tanh_fast(float x) {
    float xc = fminf(fmaxf(x, -15.0f), 15.0f);
    float e  = __expf(2.0f * xc);
    return __fdividef(e - 1.0f, e + 1.0f);
}

#define MBAR_WAIT(addr, parity)                                              \
    asm volatile(                                                            \
        "{\n\t.reg .pred P;\n"                                               \
        "W%=:\n\t"                                                           \
        "mbarrier.try_wait.parity.acquire.cta.shared::cta.b64 P, [%0], %1, 0x989680;\n\t" \
        "@!P bra W%=;\n\t}"                                                  \
        :: "r"(addr), "r"(parity) : "memory")

// =====================================================================
// Kernel 1: x_proj[t,b,j] = sum_k inputs[t,b,k] * W_ih[j,k] + b_ih[j] + b_hh[j]
// grid = 2048 (one t per CTA), 256 threads, f32x2 paired over k.
// =====================================================================
#define WPAD 130

__global__ __launch_bounds__(256) void xproj_kernel(
    const float* __restrict__ x, const float* __restrict__ Wih,
    const float* __restrict__ bih, const float* __restrict__ bhh)
{
    extern __shared__ float sm[];
    float* Wsm = sm;                    // [256][WPAD]
    float* Xsm = sm + 256 * WPAD;       // [64][128]
    const int t = blockIdx.x, tid = threadIdx.x;

    for (int i = tid; i < 256 * 128; i += 256) {
        int j = i >> 7, k = i & 127;
        Wsm[j * WPAD + k] = Wih[i];
    }
    const float* xt = x + (size_t)t * BB * DD;
    for (int i = tid; i < BB * DD; i += 256) Xsm[i] = xt[i];
    __syncthreads();

    const int bx = tid >> 5;
    const int jx = tid & 31;

    float bsum[8];
#pragma unroll
    for (int c = 0; c < 8; c++) {
        int j = jx + 32 * c;
        bsum[c] = bih[j] + bhh[j];
    }

    unsigned long long acc[8][8];
#pragma unroll
    for (int b = 0; b < 8; b++)
#pragma unroll
        for (int c = 0; c < 8; c++) acc[b][c] = 0ULL;

    const unsigned long long* Wu = (const unsigned long long*)Wsm;  // row stride 65
    const unsigned long long* Xu = (const unsigned long long*)Xsm;  // row stride 64

#pragma unroll 2
    for (int kp = 0; kp < 64; kp++) {
        unsigned long long w[8];
#pragma unroll
        for (int c = 0; c < 8; c++) w[c] = Wu[(jx + 32 * c) * 65 + kp];
#pragma unroll
        for (int b = 0; b < 8; b++) {
            unsigned long long a = Xu[(bx * 8 + b) * 64 + kp];
#pragma unroll
            for (int c = 0; c < 8; c++) FMA2(acc[b][c], w[c], a);
        }
    }

    float* op = g_xproj + (size_t)t * BB * HH;
#pragma unroll
    for (int b = 0; b < 8; b++) {
#pragma unroll
        for (int c = 0; c < 8; c++) {
            float2 f = up2(acc[b][c]);
            op[(bx * 8 + b) * HH + jx + 32 * c] = f.x + f.y + bsum[c];
        }
    }
}

// =====================================================================
// Kernel 2: persistent recurrence + head.
// 64 clusters of 2 CTAs (one batch each). CTA rank r holds W_hh rows
// [128r,128r+128) in registers. Per step: f32x2 matvec from local hbuf,
// smem reduce, tanh, then 128 st.async pushes of the new half into the
// peer's hbuf with mbarrier complete_tx (single expect_tx arrival,
// ZERO remote arrives). Only remote-half warps wait on the mbarrier,
// overlapping DSMEM fabric latency with the local-half matvec.
// =====================================================================
__global__ void __launch_bounds__(1024, 1) __cluster_dims__(2, 1, 1)
rnn_kernel(const float* __restrict__ Whh, const float* __restrict__ Wfc,
           const float* __restrict__ bfc, float* __restrict__ out)
{
    __shared__ __align__(16) float hbuf[2][HH];
    __shared__ float psum[1024];
    __shared__ __align__(8) unsigned long long mbar_store;
    __shared__ float logits_sm[8];

    const int tid  = threadIdx.x;
    const int rank = blockIdx.x & 1;
    const int b    = blockIdx.x >> 1;
    const int jl   = tid & 127;   // output row within this CTA's half
    const int g    = tid >> 7;    // k-group (32 k each), warp-uniform
    const bool remote_warp = ((g >> 2) != rank);  // this warp's k-half lives in peer-produced data

    // --- W_hh slice into registers: rows rank*128+jl, k in [32g, 32g+32) ---
    unsigned long long W2[16];
    {
        const ulonglong2* p =
            (const ulonglong2*)(Whh + (size_t)(rank * 128 + jl) * HH + g * 32);
#pragma unroll
        for (int m = 0; m < 8; m++) {
            ulonglong2 v = p[m];
            W2[2 * m]     = v.x;
            W2[2 * m + 1] = v.y;
        }
    }

    // h0 = 0 (both halves local)
    for (int i = tid; i < HH; i += 1024) hbuf[0][i] = 0.0f;

    const uint32_t mbar_local = smem_u32(&mbar_store);
    if (tid == 0) {
        asm volatile("mbarrier.init.shared.b64 [%0], %1;"
                     :: "r"(mbar_local), "r"(1) : "memory");
    }
    __syncthreads();
    // peer mbarrier must be initialized before any st.async targets it
    asm volatile("barrier.cluster.arrive.aligned;" ::: "memory");
    asm volatile("barrier.cluster.wait.aligned;" ::: "memory");

    const uint32_t peer = rank ^ 1;
    uint32_t mbar_peer, hbuf_peer;
    asm("mapa.shared::cluster.u32 %0, %1, %2;" : "=r"(mbar_peer)
        : "r"(mbar_local), "r"(peer));
    asm("mapa.shared::cluster.u32 %0, %1, %2;" : "=r"(hbuf_peer)
        : "r"(smem_u32(&hbuf[0][0])), "r"(peer));

    const float* xrow = g_xproj + (size_t)b * HH + rank * 128 + tid;  // tid<128 only
    const int xstride = BB * HH;

    int p = 0;
    float xp_cur = 0.0f, xp_next = 0.0f;
    if (tid < 128) xp_cur = xrow[0];

    for (int t = 0; t < TT; t++) {
        if (tid < 128 && t + 1 < TT) xp_next = xrow[(size_t)(t + 1) * xstride];

        // remote-half warps wait for peer's push of h_{t-1}'s other half
        if (remote_warp && t > 0) MBAR_WAIT(mbar_local, (t - 1) & 1);

        // --- matvec partial over k in [32g, 32g+32), 4 accumulators ---
        const ulonglong2* hu = (const ulonglong2*)(&hbuf[p][g * 32]);
        unsigned long long a0 = 0ULL, a1 = 0ULL, a2 = 0ULL, a3 = 0ULL;
#pragma unroll
        for (int mm = 0; mm < 4; mm++) {
            ulonglong2 h0 = hu[2 * mm];
            ulonglong2 h1 = hu[2 * mm + 1];
            FMA2(a0, W2[4 * mm],     h0.x);
            FMA2(a1, W2[4 * mm + 1], h0.y);
            FMA2(a2, W2[4 * mm + 2], h1.x);
            FMA2(a3, W2[4 * mm + 3], h1.y);
        }
        float2 f0 = up2(a0), f1 = up2(a1), f2 = up2(a2), f3 = up2(a3);
        psum[tid] = ((f0.x + f0.y) + (f1.x + f1.y)) + ((f2.x + f2.y) + (f3.x + f3.y));
        __syncthreads();

        // --- reduce 8 partials, tanh, publish (local STS + st.async push) ---
        if (tid < 128) {
            float r0 = psum[tid]       + psum[tid + 128];
            float r1 = psum[tid + 256] + psum[tid + 384];
            float r2 = psum[tid + 512] + psum[tid + 640];
            float r3 = psum[tid + 768] + psum[tid + 896];
            float hn = tanh_fast(((r0 + r1) + (r2 + r3)) + xp_cur);
            int pn = p ^ 1;
            hbuf[pn][rank * 128 + tid] = hn;  // own copy
            // push to peer with transaction-counted completion (no remote arrive)
            if ((rank == 1) || (t + 1 < TT)) {
                uint32_t dst = hbuf_peer + (uint32_t)((pn * HH + rank * 128 + tid) * 4);
                asm volatile(
                    "st.async.shared::cluster.mbarrier::complete_tx::bytes.b32 [%0], %1, [%2];"
                    :: "r"(dst), "r"(__float_as_uint(hn)), "r"(mbar_peer) : "memory");
            }
        }
        // local expect: 1 arrival + 512B tx completes phase t&1
        if (tid == 0 && ((rank == 0) || (t + 1 < TT))) {
            asm volatile("mbarrier.arrive.expect_tx.shared.b64 _, [%0], %1;"
                         :: "r"(mbar_local), "r"(512) : "memory");
        }
        __syncthreads();  // own half visible CTA-wide before next step

        p ^= 1;
        xp_cur = xp_next;
    }

    // --- head: rank 0 waits for rank1's final push, then logits + log_softmax ---
    if (rank == 0) {
        MBAR_WAIT(mbar_local, 1);  // phase 2047 (parity 1): rank1's last half
        // p == 0 here; hbuf[0] holds complete h_last
        const int w = tid >> 5, l = tid & 31;
        if (w < CC) {
            float s = 0.0f;
#pragma unroll
            for (int q = 0; q < 8; q++)
                s += hbuf[0][l + 32 * q] * Wfc[w * HH + l + 32 * q];
#pragma unroll
            for (int off = 16; off > 0; off >>= 1)
                s += __shfl_xor_sync(0xffffffffu, s, off);
            if (l == 0) logits_sm[w] = s + bfc[w];
        }
        __syncthreads();
        if (tid == 0) {
            float m = logits_sm[0];
#pragma unroll
            for (int c = 1; c < CC; c++) m = fmaxf(m, logits_sm[c]);
            float se = 0.0f;
#pragma unroll
            for (int c = 0; c < CC; c++) se += expf(logits_sm[c] - m);
            float lse = logf(se);
#pragma unroll
            for (int c = 0; c < CC; c++)
                out[b * CC + c] = logits_sm[c] - m - lse;
        }
    }
}

// =====================================================================
// launch
// =====================================================================
extern "C" void kernel_launch(void* const* d_in, const int* in_sizes, int n_in,
                              void* d_out, int out_size)
{
    const float* inputs = (const float*)d_in[0];
    const float* W_ih   = (const float*)d_in[1];
    const float* W_hh   = (const float*)d_in[2];
    const float* b_ih   = (const float*)d_in[3];
    const float* b_hh   = (const float*)d_in[4];
    const float* W_fc   = (const float*)d_in[5];
    const float* b_fc   = (const float*)d_in[6];
    float* out = (float*)d_out;

    const int smem1 = (256 * WPAD + BB * DD) * (int)sizeof(float);  // ~166 KB
    static int configured = 0;
    if (!configured) {
        cudaFuncSetAttribute(xproj_kernel,
                             cudaFuncAttributeMaxDynamicSharedMemorySize, smem1);
        configured = 1;
    }

    xproj_kernel<<<TT, 256, smem1>>>(inputs, W_ih, b_ih, b_hh);
    rnn_kernel<<<2 * BB, 1024>>>(W_hh, W_fc, b_fc, out);
}